// round 16
// baseline (speedup 1.0000x reference)
#include <cuda_runtime.h>
#include <cuda_fp16.h>
#include <cstdint>

// ---------------------------------------------------------------------------
// 608MB arena. Regions (single writer before readers):
//   [0,128)   S fp32 scores -> fp16 P in place (row r at byte 4096*r)
//   [128,144) Xh   [144,160) Xl
//   [160,224) Yh   [224,288) Yl          Y = X*M per (h,b)
//   [288,352) VOh                        VO = X*M2 per (h,b), hi only
//   [416,432) Mh   [432,448) Ml          M  = W_Q W_K^T per h (22-bit pair)
//   [448,464) M2h                        M2 = W_V W_O_h per h (hi only)
//   [480,608) plain W splits: WQ h/l, WK h/l, WV h/l, WO h/l (16MB each)
// ---------------------------------------------------------------------------
__device__ __align__(1024) unsigned char g_arena[(size_t)608 << 20];

#define A_P     ((size_t)0)
#define A_XH    ((size_t)128 << 20)
#define A_XL    ((size_t)144 << 20)
#define A_YH    ((size_t)160 << 20)
#define A_YL    ((size_t)224 << 20)
#define A_VOH   ((size_t)288 << 20)
#define A_MH    ((size_t)416 << 20)
#define A_ML    ((size_t)432 << 20)
#define A_M2H   ((size_t)448 << 20)
#define A_WQH   ((size_t)480 << 20)
#define A_WQL   ((size_t)496 << 20)
#define A_WKH   ((size_t)512 << 20)
#define A_WKL   ((size_t)528 << 20)
#define A_WVH   ((size_t)544 << 20)
#define A_WVL   ((size_t)560 << 20)
#define A_WOH   ((size_t)576 << 20)
#define A_WOL   ((size_t)592 << 20)

__device__ __forceinline__ __half* PH(size_t o) { return reinterpret_cast<__half*>(g_arena + o); }
__device__ __forceinline__ float*  PF(size_t o) { return reinterpret_cast<float*>(g_arena + o); }

// ---------------------------------------------------------------------------
// helpers
// ---------------------------------------------------------------------------
__device__ __forceinline__ void mma_f16(float* d, const uint32_t* a, uint32_t b0, uint32_t b1) {
    asm volatile("mma.sync.aligned.m16n8k16.row.col.f32.f16.f16.f32 "
                 "{%0,%1,%2,%3}, {%4,%5,%6,%7}, {%8,%9}, {%0,%1,%2,%3};"
                 : "+f"(d[0]), "+f"(d[1]), "+f"(d[2]), "+f"(d[3])
                 : "r"(a[0]), "r"(a[1]), "r"(a[2]), "r"(a[3]), "r"(b0), "r"(b1));
}
__device__ __forceinline__ uint32_t h2u(__half2 h) { return *reinterpret_cast<uint32_t*>(&h); }
__device__ __forceinline__ void split_h2(float a, float b, uint32_t& hi, uint32_t& lo) {
    __half2 h = __floats2half2_rn(a, b);
    float2 hf = __half22float2(h);
    __half2 l = __floats2half2_rn(a - hf.x, b - hf.y);
    hi = h2u(h); lo = h2u(l);
}

// ---------------------------------------------------------------------------
// 3-pass fp16 GEMM (UNCHANGED, proven): C[128x128]/CTA, Kc=16.
// Passes hh, hl, lh (ALO/BLO both true for all users here).
// BMODE 1: B plain halves [n][k] (producer transposes into smem)
// BMODE 2: B plain halves [k][n] (producer PRMT-interleaves), ldb
// EPI 0: fp32 C0;  EPI 1: fp16 hi(C0)+lo(C1)
// ---------------------------------------------------------------------------
template <int BMODE, int EPI>
__device__ __forceinline__ void gemm3p(
    const __half* __restrict__ Ah, const __half* __restrict__ Al, int lda,
    const __half* __restrict__ Bh, const __half* __restrict__ Bl, int ldb,
    void* __restrict__ C0, void* __restrict__ C1, int ldc,
    int K, float alpha)
{
    __shared__ uint32_t sAh[128 * 12];
    __shared__ uint32_t sAl[128 * 12];
    __shared__ uint32_t sBh[8 * 136];
    __shared__ uint32_t sBl[8 * 136];

    const int tid = threadIdx.x, lane = tid & 31, wid = tid >> 5;
    const int g = lane >> 2, c = lane & 3;
    const int wm = wid & 1, wn = wid >> 1;
    const int row0 = blockIdx.y * 128, col0 = blockIdx.x * 128;

    const int am = tid >> 1, akh = (tid & 1) * 8;
    const __half* pAh = Ah + (size_t)(row0 + am) * lda + akh;
    const __half* pAl = Al + (size_t)(row0 + am) * lda + akh;

    const __half* pBNh = Bh;
    const __half* pBNl = Bl;
    const __half* pBVh = Bh;
    const __half* pBVl = Bl;
    if (BMODE == 1) {
        pBNh += (size_t)(col0 + am) * ldb + akh;
        pBNl += (size_t)(col0 + am) * ldb + akh;
    } else {
        pBVh += (size_t)(wid * 2) * ldb + col0 + (lane << 2);
        pBVl += (size_t)(wid * 2) * ldb + col0 + (lane << 2);
    }

    uint4 rAh, rAl, rBh4, rBl4;
    uint2 rV0h, rV1h, rV0l, rV1l;
    const int NC = K >> 4;

    auto ldg = [&](int i) {
        rAh = *reinterpret_cast<const uint4*>(pAh + (size_t)i * 16);
        rAl = *reinterpret_cast<const uint4*>(pAl + (size_t)i * 16);
        if (BMODE == 1) {
            rBh4 = *reinterpret_cast<const uint4*>(pBNh + (size_t)i * 16);
            rBl4 = *reinterpret_cast<const uint4*>(pBNl + (size_t)i * 16);
        } else {
            const __half* b0 = pBVh + (size_t)i * 16 * ldb;
            rV0h = *reinterpret_cast<const uint2*>(b0);
            rV1h = *reinterpret_cast<const uint2*>(b0 + ldb);
            const __half* b1 = pBVl + (size_t)i * 16 * ldb;
            rV0l = *reinterpret_cast<const uint2*>(b1);
            rV1l = *reinterpret_cast<const uint2*>(b1 + ldb);
        }
    };
    auto sts = [&]() {
        const int ao = am * 12 + (akh >> 1);
        *reinterpret_cast<uint4*>(&sAh[ao]) = rAh;
        *reinterpret_cast<uint4*>(&sAl[ao]) = rAl;
        if (BMODE == 1) {
            const int kj = akh >> 1;
            sBh[(kj + 0) * 136 + am] = rBh4.x;
            sBh[(kj + 1) * 136 + am] = rBh4.y;
            sBh[(kj + 2) * 136 + am] = rBh4.z;
            sBh[(kj + 3) * 136 + am] = rBh4.w;
            sBl[(kj + 0) * 136 + am] = rBl4.x;
            sBl[(kj + 1) * 136 + am] = rBl4.y;
            sBl[(kj + 2) * 136 + am] = rBl4.z;
            sBl[(kj + 3) * 136 + am] = rBl4.w;
        } else {
            const int bo = wid * 136 + (lane << 2);
            uint4 w;
            w.x = __byte_perm(rV0h.x, rV1h.x, 0x5410);
            w.y = __byte_perm(rV0h.x, rV1h.x, 0x7632);
            w.z = __byte_perm(rV0h.y, rV1h.y, 0x5410);
            w.w = __byte_perm(rV0h.y, rV1h.y, 0x7632);
            *reinterpret_cast<uint4*>(&sBh[bo]) = w;
            uint4 u;
            u.x = __byte_perm(rV0l.x, rV1l.x, 0x5410);
            u.y = __byte_perm(rV0l.x, rV1l.x, 0x7632);
            u.z = __byte_perm(rV0l.y, rV1l.y, 0x5410);
            u.w = __byte_perm(rV0l.y, rV1l.y, 0x7632);
            *reinterpret_cast<uint4*>(&sBl[bo]) = u;
        }
    };

    float acc[4][4][4];
#pragma unroll
    for (int a = 0; a < 4; a++)
#pragma unroll
        for (int b = 0; b < 4; b++)
#pragma unroll
            for (int d = 0; d < 4; d++) acc[a][b][d] = 0.0f;

    ldg(0);
    for (int i = 0; i < NC; i++) {
        sts();
        __syncthreads();
        if (i + 1 < NC) ldg(i + 1);

        uint32_t fbh[4][2], fbl[4][2];
#pragma unroll
        for (int nj = 0; nj < 4; nj++) {
            const int n = wn * 32 + nj * 8 + g;
            fbh[nj][0] = sBh[c * 136 + n];
            fbh[nj][1] = sBh[(c + 4) * 136 + n];
            fbl[nj][0] = sBl[c * 136 + n];
            fbl[nj][1] = sBl[(c + 4) * 136 + n];
        }
#pragma unroll
        for (int mi = 0; mi < 4; mi++) {
            const int r = (wm * 64 + mi * 16 + g) * 12 + c;
            uint32_t fa[4], fl[4];
            fa[0] = sAh[r];      fa[1] = sAh[r + 96];
            fa[2] = sAh[r + 4];  fa[3] = sAh[r + 100];
            fl[0] = sAl[r];      fl[1] = sAl[r + 96];
            fl[2] = sAl[r + 4];  fl[3] = sAl[r + 100];
#pragma unroll
            for (int nj = 0; nj < 4; nj++) {
                mma_f16(acc[mi][nj], fa, fbh[nj][0], fbh[nj][1]);   // hh
                mma_f16(acc[mi][nj], fa, fbl[nj][0], fbl[nj][1]);   // hl
                mma_f16(acc[mi][nj], fl, fbh[nj][0], fbh[nj][1]);   // lh
            }
        }
        __syncthreads();
    }

#pragma unroll
    for (int mi = 0; mi < 4; mi++) {
        const int r = row0 + wm * 64 + mi * 16 + g;
#pragma unroll
        for (int nj = 0; nj < 4; nj++) {
            const int cc = col0 + wn * 32 + nj * 8 + c * 2;
            float2 v0 = make_float2(acc[mi][nj][0] * alpha, acc[mi][nj][1] * alpha);
            float2 v1 = make_float2(acc[mi][nj][2] * alpha, acc[mi][nj][3] * alpha);
            if (EPI == 0) {
                *reinterpret_cast<float2*>((float*)C0 + (size_t)r * ldc + cc)       = v0;
                *reinterpret_cast<float2*>((float*)C0 + (size_t)(r + 8) * ldc + cc) = v1;
            } else {
                __half2 h0 = __floats2half2_rn(v0.x, v0.y);
                __half2 h1 = __floats2half2_rn(v1.x, v1.y);
                *reinterpret_cast<__half2*>((__half*)C0 + (size_t)r * ldc + cc)       = h0;
                *reinterpret_cast<__half2*>((__half*)C0 + (size_t)(r + 8) * ldc + cc) = h1;
                float2 f0 = __half22float2(h0), f1 = __half22float2(h1);
                __half2 l0 = __floats2half2_rn(v0.x - f0.x, v0.y - f0.y);
                __half2 l1 = __floats2half2_rn(v1.x - f1.x, v1.y - f1.y);
                *reinterpret_cast<__half2*>((__half*)C1 + (size_t)r * ldc + cc)       = l0;
                *reinterpret_cast<__half2*>((__half*)C1 + (size_t)(r + 8) * ldc + cc) = l1;
            }
        }
    }
}

// ---------------------------------------------------------------------------
// 1-pass fp16 GEMM, Kc=32: C[128x128]/CTA. 32 MMAs per sync (2 k-steps),
// halved barrier count, 2x ldg->sts slack. smem 18.9KB -> 2 CTAs/SM.
// AMODE 0: A plain [m][k], lda
// AMODE 1: A = P-concat (k=h*1024+s; b=row0>>10; P rows strided 2048)
// BMODE 0: B plain [k][n], ldb
// BMODE 1: B = VO-concat ([s][n] 1024x1024 blocks; h-stride 4M halves, +b*1M)
// EPI 0: fp32;  EPI 2: fp16 hi only
// ---------------------------------------------------------------------------
template <int AMODE, int BMODE, int EPI>
__device__ __forceinline__ void gemm1p(
    const __half* __restrict__ Ah, int lda,
    const __half* __restrict__ Bh, int ldb,
    void* __restrict__ C, int ldc, int K, float alpha)
{
    __shared__ uint32_t sA[128 * 20];     // pitch 20 words: conflict-free frags
    __shared__ uint32_t sB[16 * 136];

    const int tid = threadIdx.x, lane = tid & 31, wid = tid >> 5;
    const int g = lane >> 2, c = lane & 3;
    const int wm = wid & 1, wn = wid >> 1;
    const int row0 = blockIdx.y * 128, col0 = blockIdx.x * 128;
    const int bb = row0 >> 10;

    // A producer: row am, 16 consecutive halves at sel*16
    const int am = tid >> 1, sel = tid & 1;
    const __half* pA;
    if (AMODE == 0) pA = Ah + (size_t)(row0 + am) * lda + sel * 16;
    else {
        const int q = (row0 + am) & 1023;
        pA = Ah + (size_t)bb * 2097152 + (size_t)q * 2048 + sel * 16;
    }

    uint4 rA0, rA1;
    uint2 rB[2][2];
    const int NC = K >> 5;

    auto ldg = [&](int i) {
        const __half* a = (AMODE == 0)
            ? pA + (size_t)i * 32
            : pA + (size_t)(i >> 5) * 8388608 + (size_t)(i & 31) * 32;
        rA0 = *reinterpret_cast<const uint4*>(a);
        rA1 = *reinterpret_cast<const uint4*>(a + 8);
#pragma unroll
        for (int r = 0; r < 2; r++) {
            const int kp = wid + 8 * r;            // kpair 0..15
            const __half* b;
            int rstride;
            if (BMODE == 0) {
                b = Bh + (size_t)(i * 32 + 2 * kp) * ldb + col0 + lane * 4;
                rstride = ldb;
            } else {
                b = Bh + (size_t)(i >> 5) * 4194304 + (size_t)bb * 1048576
                  + (size_t)((i & 31) * 32 + 2 * kp) * 1024 + col0 + lane * 4;
                rstride = 1024;
            }
            rB[r][0] = *reinterpret_cast<const uint2*>(b);
            rB[r][1] = *reinterpret_cast<const uint2*>(b + rstride);
        }
    };
    auto sts = [&]() {
        const int ao = am * 20 + sel * 8;
        *reinterpret_cast<uint4*>(&sA[ao])     = rA0;
        *reinterpret_cast<uint4*>(&sA[ao + 4]) = rA1;
#pragma unroll
        for (int r = 0; r < 2; r++) {
            const int kp = wid + 8 * r;
            uint4 w;
            w.x = __byte_perm(rB[r][0].x, rB[r][1].x, 0x5410);
            w.y = __byte_perm(rB[r][0].x, rB[r][1].x, 0x7632);
            w.z = __byte_perm(rB[r][0].y, rB[r][1].y, 0x5410);
            w.w = __byte_perm(rB[r][0].y, rB[r][1].y, 0x7632);
            *reinterpret_cast<uint4*>(&sB[kp * 136 + lane * 4]) = w;
        }
    };

    float acc[4][4][4];
#pragma unroll
    for (int a = 0; a < 4; a++)
#pragma unroll
        for (int b = 0; b < 4; b++)
#pragma unroll
            for (int d = 0; d < 4; d++) acc[a][b][d] = 0.0f;

    ldg(0);
    for (int i = 0; i < NC; i++) {
        sts();
        __syncthreads();
        if (i + 1 < NC) ldg(i + 1);

#pragma unroll
        for (int ks = 0; ks < 2; ks++) {
            uint32_t fbh[4][2];
#pragma unroll
            for (int nj = 0; nj < 4; nj++) {
                const int n = wn * 32 + nj * 8 + g;
                fbh[nj][0] = sB[(ks * 8 + c) * 136 + n];
                fbh[nj][1] = sB[(ks * 8 + c + 4) * 136 + n];
            }
#pragma unroll
            for (int mi = 0; mi < 4; mi++) {
                const int r = (wm * 64 + mi * 16 + g) * 20 + ks * 8 + c;
                uint32_t fa[4];
                fa[0] = sA[r];      fa[1] = sA[r + 160];   // +8 rows * 20
                fa[2] = sA[r + 4];  fa[3] = sA[r + 164];
#pragma unroll
                for (int nj = 0; nj < 4; nj++)
                    mma_f16(acc[mi][nj], fa, fbh[nj][0], fbh[nj][1]);
            }
        }
        __syncthreads();
    }

#pragma unroll
    for (int mi = 0; mi < 4; mi++) {
        const int r = row0 + wm * 64 + mi * 16 + g;
#pragma unroll
        for (int nj = 0; nj < 4; nj++) {
            const int cc = col0 + wn * 32 + nj * 8 + c * 2;
            float2 v0 = make_float2(acc[mi][nj][0] * alpha, acc[mi][nj][1] * alpha);
            float2 v1 = make_float2(acc[mi][nj][2] * alpha, acc[mi][nj][3] * alpha);
            if (EPI == 0) {
                *reinterpret_cast<float2*>((float*)C + (size_t)r * ldc + cc)       = v0;
                *reinterpret_cast<float2*>((float*)C + (size_t)(r + 8) * ldc + cc) = v1;
            } else {
                __half2 h0 = __floats2half2_rn(v0.x, v0.y);
                __half2 h1 = __floats2half2_rn(v1.x, v1.y);
                *reinterpret_cast<__half2*>((__half*)C + (size_t)r * ldc + cc)       = h0;
                *reinterpret_cast<__half2*>((__half*)C + (size_t)(r + 8) * ldc + cc) = h1;
            }
        }
    }
}

// ---------------------------------------------------------------------------
// GEMM wrapper kernels (one template instantiation per kernel -> 2 CTAs/SM)
// ---------------------------------------------------------------------------
// M_h = WQ_h @ WK_h^T (3-pass, hi+lo out)
__global__ __launch_bounds__(256, 2) void k_m()
{
    const size_t h = blockIdx.z;
    gemm3p<1, 1>(PH(A_WQH) + h * 1048576, PH(A_WQL) + h * 1048576, 1024,
                 PH(A_WKH) + h * 1048576, PH(A_WKL) + h * 1048576, 1024,
                 PH(A_MH) + h * 1048576, PH(A_ML) + h * 1048576, 1024,
                 1024, 1.0f);
}

// M2_h = WV_h @ WO_h (1-pass, hi out)
__global__ __launch_bounds__(256, 2) void k_m2()
{
    const size_t h = blockIdx.z;
    gemm1p<0, 0, 2>(PH(A_WVH) + h * 1048576, 1024,
                    PH(A_WOH) + h * 1048576, 1024,
                    PH(A_M2H) + h * 1048576, 1024, 1024, 1.0f);
}

// Y_hb = X_b @ M_h (3-pass, hi+lo out)
__global__ __launch_bounds__(256, 2) void k_y()
{
    const size_t z = blockIdx.z, h = z >> 2, b = z & 3;
    gemm3p<2, 1>(PH(A_XH) + b * 1048576, PH(A_XL) + b * 1048576, 1024,
                 PH(A_MH) + h * 1048576, PH(A_ML) + h * 1048576, 1024,
                 PH(A_YH) + z * 1048576, PH(A_YL) + z * 1048576, 1024,
                 1024, 1.0f);
}

// VO_hb = X_b @ M2_h (1-pass, hi out)
__global__ __launch_bounds__(256, 2) void k_vo()
{
    const size_t z = blockIdx.z, h = z >> 2, b = z & 3;
    gemm1p<0, 0, 2>(PH(A_XH) + b * 1048576, 1024,
                    PH(A_M2H) + h * 1048576, 1024,
                    PH(A_VOH) + z * 1048576, 1024, 1024, 1.0f);
}

// S_hb = 32 * Y_hb @ X_b^T (3-pass, fp32 out)
__global__ __launch_bounds__(256, 2) void k_s()
{
    const size_t z = blockIdx.z, b = z & 3;
    gemm3p<1, 0>(PH(A_YH) + z * 1048576, PH(A_YL) + z * 1048576, 1024,
                 PH(A_XH) + b * 1048576, PH(A_XL) + b * 1048576, 1024,
                 PF(A_P) + z * 1048576, nullptr, 1024,
                 1024, 32.0f);   // sqrt(1024)
}

// out = sum_h P_hb @ VO_hb (concat-K GEMM K=8192, 1-pass)
__global__ __launch_bounds__(256, 2) void k_out(float* __restrict__ out)
{
    gemm1p<1, 1, 0>(PH(A_P), 0, PH(A_VOH), 0, out, 1024, 8192, 1.0f);
}

// ---------------------------------------------------------------------------
// merged prep: 5 hi/lo splits in one launch (grid.y selects tensor)
// ---------------------------------------------------------------------------
__global__ void k_split5(const float* __restrict__ X,  const float* __restrict__ WQ,
                         const float* __restrict__ WK, const float* __restrict__ WV,
                         const float* __restrict__ WO)
{
    const float* src;
    size_t oh, ol;
    int nblk;
    switch (blockIdx.y) {
    case 0:  src = X;  oh = A_XH;  ol = A_XL;  nblk = 4096; break;
    case 1:  src = WQ; oh = A_WQH; ol = A_WQL; nblk = 8192; break;
    case 2:  src = WK; oh = A_WKH; ol = A_WKL; nblk = 8192; break;
    case 3:  src = WV; oh = A_WVH; ol = A_WVL; nblk = 8192; break;
    default: src = WO; oh = A_WOH; ol = A_WOL; nblk = 8192; break;
    }
    if ((int)blockIdx.x >= nblk) return;
    const size_t i = (size_t)blockIdx.x * 256 + threadIdx.x;
    float4 v = reinterpret_cast<const float4*>(src)[i];
    uint32_t h0, l0, h1, l1;
    split_h2(v.x, v.y, h0, l0);
    split_h2(v.z, v.w, h1, l1);
    reinterpret_cast<uint2*>(PH(oh))[i] = make_uint2(h0, h1);
    reinterpret_cast<uint2*>(PH(ol))[i] = make_uint2(l0, l1);
}

// ---------------------------------------------------------------------------
// softmax: fp32 scores row -> fp16 probs IN PLACE (row r at byte 4096*r)
// ---------------------------------------------------------------------------
__global__ void k_softmax()
{
    __shared__ float red[8];
    const size_t row = blockIdx.x;
    const float* p = PF(A_P) + row * 1024;
    const int t = threadIdx.x;

    float4 x = reinterpret_cast<const float4*>(p)[t];
    float m = fmaxf(fmaxf(x.x, x.y), fmaxf(x.z, x.w));
#pragma unroll
    for (int o = 16; o; o >>= 1) m = fmaxf(m, __shfl_xor_sync(0xffffffffu, m, o));
    if ((t & 31) == 0) red[t >> 5] = m;
    __syncthreads();
    if (t < 8) {
        float mm = red[t];
#pragma unroll
        for (int o = 4; o; o >>= 1) mm = fmaxf(mm, __shfl_xor_sync(0xffu, mm, o));
        red[t] = mm;
    }
    __syncthreads();
    m = red[0];
    __syncthreads();

    x.x = expf(x.x - m); x.y = expf(x.y - m);
    x.z = expf(x.z - m); x.w = expf(x.w - m);
    float s = x.x + x.y + x.z + x.w;
#pragma unroll
    for (int o = 16; o; o >>= 1) s += __shfl_xor_sync(0xffffffffu, s, o);
    if ((t & 31) == 0) red[t >> 5] = s;
    __syncthreads();
    if (t < 8) {
        float ss = red[t];
#pragma unroll
        for (int o = 4; o; o >>= 1) ss += __shfl_xor_sync(0xffu, ss, o);
        red[t] = ss;
    }
    __syncthreads();
    const float inv = 1.0f / red[0];
    x.x *= inv; x.y *= inv; x.z *= inv; x.w *= inv;

    __half2 p0 = __floats2half2_rn(x.x, x.y);
    __half2 p1 = __floats2half2_rn(x.z, x.w);
    *reinterpret_cast<uint2*>(PH(A_P) + row * 2048 + 4 * t) = make_uint2(h2u(p0), h2u(p1));
}

// ---------------------------------------------------------------------------
// Inputs: input, input_mask, W_Q, W_K, W_V, W_O
// ---------------------------------------------------------------------------
extern "C" void kernel_launch(void* const* d_in, const int* in_sizes, int n_in,
                              void* d_out, int out_size)
{
    const float* X  = (const float*)d_in[0];
    const float* WQ = (const float*)d_in[2];
    const float* WK = (const float*)d_in[3];
    const float* WV = (const float*)d_in[4];
    const float* WO = (const float*)d_in[5];
    float* out = (float*)d_out;

    k_split5<<<dim3(8192, 5), 256>>>(X, WQ, WK, WV, WO);
    k_m  <<<dim3(8, 8, 8), 256>>>();
    k_m2 <<<dim3(8, 8, 8), 256>>>();
    k_y  <<<dim3(8, 8, 32), 256>>>();
    k_vo <<<dim3(8, 8, 32), 256>>>();
    k_s  <<<dim3(8, 8, 32), 256>>>();
    k_softmax<<<32768, 256>>>();
    k_out<<<dim3(8, 32), 256>>>(out);
}